// round 1
// baseline (speedup 1.0000x reference)
#include <cuda_runtime.h>
#include <cuda_bf16.h>
#include <math_constants.h>

#define BATCH 8
#define C_DIM 256
#define HW    4096
#define T_DIM 512

// 1/sqrt(512)
#define SCALE 0.044194173824159220275f

// Softmax probabilities scratch: [B][HW][T] fp32 = 64 MiB (device global, allowed)
__device__ float g_S[(size_t)BATCH * HW * T_DIM];

// ---------------- packed f32x2 helpers (sm_103a FFMA2) ----------------
__device__ __forceinline__ unsigned long long pack2(float lo, float hi) {
    unsigned long long r;
    asm("mov.b64 %0, {%1, %2};" : "=l"(r) : "f"(lo), "f"(hi));
    return r;
}
__device__ __forceinline__ void unpack2(unsigned long long v, float& lo, float& hi) {
    asm("mov.b64 {%0, %1}, %2;" : "=f"(lo), "=f"(hi) : "l"(v));
}
__device__ __forceinline__ unsigned long long ffma2(unsigned long long a,
                                                    unsigned long long b,
                                                    unsigned long long c) {
    unsigned long long d;
    asm("fma.rn.f32x2 %0, %1, %2, %3;" : "=l"(d) : "l"(a), "l"(b), "l"(c));
    return d;
}

// =====================================================================
// Kernel 1: scores + softmax.
// S[b][n][t] = softmax_t( (F_s_t[n,:] . F_t[t,:]) * SCALE )
// Block: 32 rows (n) x full T=512 cols. 256 threads.
// Thread (rtile = warp 0..7, ctile = lane 0..31):
//   rows  n = n0 + rtile*4 + m        (m = 0..3)
//   cols  t = 2*ctile + 64*j + {0,1}  (j = 0..7)  -> 16 cols/thread
// Each row lives entirely inside one warp -> shfl softmax.
// =====================================================================
__global__ __launch_bounds__(256) void k1_scores_softmax(
    const float* __restrict__ Fs, const float* __restrict__ Ft)
{
    __shared__ __align__(16) float As[16][32];    // [k][n]
    __shared__ __align__(16) float Bs[16][514];   // [k][t], stride 514 (conflict-free)

    const int b  = blockIdx.y;
    const int n0 = blockIdx.x * 32;
    const float* FsB = Fs + (size_t)b * C_DIM * HW;
    const float* FtB = Ft + (size_t)b * T_DIM * C_DIM;

    const int tid   = threadIdx.x;
    const int ctile = tid & 31;
    const int rtile = tid >> 5;   // warp id == row-group

    unsigned long long acc2[4][8];
#pragma unroll
    for (int m = 0; m < 4; m++)
#pragma unroll
        for (int j = 0; j < 8; j++) acc2[m][j] = 0ULL;

    for (int k0 = 0; k0 < C_DIM; k0 += 16) {
        // A tile: 32 n x 16 k. F_s[c][n] contiguous in n -> coalesced.
#pragma unroll
        for (int r = 0; r < 2; r++) {
            int idx = tid + r * 256;
            int kk = idx >> 5, nn = idx & 31;
            As[kk][nn] = FsB[(size_t)(k0 + kk) * HW + n0 + nn];
        }
        // B tile: 16 k x 512 t. F_t[t][c] contiguous in c(k).
#pragma unroll
        for (int r = 0; r < 32; r++) {
            int idx = tid + r * 256;
            int tt = idx >> 4, kk = idx & 15;
            Bs[kk][tt] = FtB[(size_t)tt * C_DIM + k0 + kk];
        }
        __syncthreads();

#pragma unroll
        for (int k = 0; k < 16; k++) {
            float4 av = *reinterpret_cast<const float4*>(&As[k][rtile * 4]);
            unsigned long long a2[4];
            a2[0] = pack2(av.x, av.x);
            a2[1] = pack2(av.y, av.y);
            a2[2] = pack2(av.z, av.z);
            a2[3] = pack2(av.w, av.w);
            unsigned long long b2[8];
#pragma unroll
            for (int j = 0; j < 8; j++)
                b2[j] = *reinterpret_cast<const unsigned long long*>(
                            &Bs[k][2 * ctile + 64 * j]);
#pragma unroll
            for (int m = 0; m < 4; m++)
#pragma unroll
                for (int j = 0; j < 8; j++)
                    acc2[m][j] = ffma2(a2[m], b2[j], acc2[m][j]);
        }
        __syncthreads();
    }

    // Softmax per row (each row fully inside this warp).
    float* Sb = g_S + (size_t)b * HW * T_DIM;
#pragma unroll
    for (int m = 0; m < 4; m++) {
        float v[16];
#pragma unroll
        for (int j = 0; j < 8; j++) unpack2(acc2[m][j], v[2 * j], v[2 * j + 1]);

        float mx = -CUDART_INF_F;
#pragma unroll
        for (int x = 0; x < 16; x++) { v[x] *= SCALE; mx = fmaxf(mx, v[x]); }
#pragma unroll
        for (int off = 16; off >= 1; off >>= 1)
            mx = fmaxf(mx, __shfl_xor_sync(0xffffffffu, mx, off));

        float s = 0.0f;
#pragma unroll
        for (int x = 0; x < 16; x++) { v[x] = __expf(v[x] - mx); s += v[x]; }
#pragma unroll
        for (int off = 16; off >= 1; off >>= 1)
            s += __shfl_xor_sync(0xffffffffu, s, off);
        float inv = 1.0f / s;

        const int n = n0 + rtile * 4 + m;
        float* dst = Sb + (size_t)n * T_DIM;
#pragma unroll
        for (int j = 0; j < 8; j++) {
            float2 p = make_float2(v[2 * j] * inv, v[2 * j + 1] * inv);
            *reinterpret_cast<float2*>(&dst[2 * ctile + 64 * j]) = p;
        }
    }
}

// =====================================================================
// Kernel 2: F_s_updated[b][c][n] = F_s[b][c][n] + sum_t S[b][n][t]*F_t[b][t][c]
// GEMM: M = c (64-tile), N = n (64-tile), K = t (512).
// Threads 256: ty = rows(c), tx = col-pairs(n).
//   rows c = c0 + ty + 16*i (i=0..3); cols n = n0 + 2*tx + 32*j + {0,1} (j=0..1)
// =====================================================================
__global__ __launch_bounds__(256) void k2_spatial(
    const float* __restrict__ Fs, const float* __restrict__ Ft,
    float* __restrict__ out)
{
    __shared__ __align__(16) float As[16][64];   // [k(t)][c]
    __shared__ __align__(16) float Bs[16][66];   // [k(t)][n], stride 66

    const int b  = blockIdx.z;
    const int n0 = blockIdx.x * 64;
    const int c0 = blockIdx.y * 64;
    const float* FsB = Fs + (size_t)b * C_DIM * HW;
    const float* FtB = Ft + (size_t)b * T_DIM * C_DIM;
    const float* Sb  = g_S + (size_t)b * HW * T_DIM;
    float* outB = out + (size_t)b * C_DIM * HW;

    const int tid = threadIdx.x;
    const int tx = tid & 15, ty = tid >> 4;

    unsigned long long acc2[4][2];
#pragma unroll
    for (int i = 0; i < 4; i++) { acc2[i][0] = 0ULL; acc2[i][1] = 0ULL; }

    for (int k0 = 0; k0 < T_DIM; k0 += 16) {
#pragma unroll
        for (int r = 0; r < 4; r++) {
            int idx = tid + r * 256;
            int kk = idx >> 6, mm = idx & 63;
            As[kk][mm] = FtB[(size_t)(k0 + kk) * C_DIM + c0 + mm];
            int nn = idx >> 4, kb = idx & 15;
            Bs[kb][nn] = Sb[(size_t)(n0 + nn) * T_DIM + k0 + kb];
        }
        __syncthreads();
#pragma unroll
        for (int k = 0; k < 16; k++) {
            unsigned long long a2[4];
#pragma unroll
            for (int i = 0; i < 4; i++) {
                float av = As[k][ty + 16 * i];
                a2[i] = pack2(av, av);
            }
            unsigned long long b2[2];
#pragma unroll
            for (int j = 0; j < 2; j++)
                b2[j] = *reinterpret_cast<const unsigned long long*>(
                            &Bs[k][2 * tx + 32 * j]);
#pragma unroll
            for (int i = 0; i < 4; i++)
#pragma unroll
                for (int j = 0; j < 2; j++)
                    acc2[i][j] = ffma2(a2[i], b2[j], acc2[i][j]);
        }
        __syncthreads();
    }

#pragma unroll
    for (int i = 0; i < 4; i++) {
        int c = c0 + ty + 16 * i;
#pragma unroll
        for (int j = 0; j < 2; j++) {
            int n = n0 + 2 * tx + 32 * j;
            float lo, hi;
            unpack2(acc2[i][j], lo, hi);
            size_t off = (size_t)c * HW + n;
            float2 fs = *reinterpret_cast<const float2*>(&FsB[off]);
            float2 r2 = make_float2(fs.x + lo, fs.y + hi);
            *reinterpret_cast<float2*>(&outB[off]) = r2;
        }
    }
}

// =====================================================================
// Kernel 3: F_t_updated[b][t][c] = sum_n S[b][n][t] * F_s_t[b][n][c]
// GEMM: M = t (64-tile), N = c (64-tile), K = n (4096).
// =====================================================================
__global__ __launch_bounds__(256) void k3_text(
    const float* __restrict__ Fs, float* __restrict__ outT)
{
    __shared__ __align__(16) float As[16][64];   // [k(n)][t]
    __shared__ __align__(16) float Bs[16][66];   // [k(n)][c], stride 66

    const int b  = blockIdx.z;
    const int t0 = blockIdx.x * 64;
    const int c0 = blockIdx.y * 64;
    const float* FsB = Fs + (size_t)b * C_DIM * HW;
    const float* Sb  = g_S + (size_t)b * HW * T_DIM;
    float* outB = outT + (size_t)b * T_DIM * C_DIM;

    const int tid = threadIdx.x;
    const int tx = tid & 15, ty = tid >> 4;

    unsigned long long acc2[4][2];
#pragma unroll
    for (int i = 0; i < 4; i++) { acc2[i][0] = 0ULL; acc2[i][1] = 0ULL; }

    for (int k0 = 0; k0 < HW; k0 += 16) {
#pragma unroll
        for (int r = 0; r < 4; r++) {
            int idx = tid + r * 256;
            int kk = idx >> 6, mm = idx & 63;
            As[kk][mm] = Sb[(size_t)(k0 + kk) * T_DIM + t0 + mm];
            int cc = idx >> 4, kb = idx & 15;
            Bs[kb][cc] = FsB[(size_t)(c0 + cc) * HW + k0 + kb];
        }
        __syncthreads();
#pragma unroll
        for (int k = 0; k < 16; k++) {
            unsigned long long a2[4];
#pragma unroll
            for (int i = 0; i < 4; i++) {
                float av = As[k][ty + 16 * i];
                a2[i] = pack2(av, av);
            }
            unsigned long long b2[2];
#pragma unroll
            for (int j = 0; j < 2; j++)
                b2[j] = *reinterpret_cast<const unsigned long long*>(
                            &Bs[k][2 * tx + 32 * j]);
#pragma unroll
            for (int i = 0; i < 4; i++)
#pragma unroll
                for (int j = 0; j < 2; j++)
                    acc2[i][j] = ffma2(a2[i], b2[j], acc2[i][j]);
        }
        __syncthreads();
    }

#pragma unroll
    for (int i = 0; i < 4; i++) {
        int t = t0 + ty + 16 * i;
#pragma unroll
        for (int j = 0; j < 2; j++) {
            int c = c0 + 2 * tx + 32 * j;
            float lo, hi;
            unpack2(acc2[i][j], lo, hi);
            *reinterpret_cast<float2*>(&outB[(size_t)t * C_DIM + c]) =
                make_float2(lo, hi);
        }
    }
}

// =====================================================================
extern "C" void kernel_launch(void* const* d_in, const int* in_sizes, int n_in,
                              void* d_out, int out_size)
{
    const float* Fs = (const float*)d_in[0];   // [B, C, H, W]
    const float* Ft = (const float*)d_in[1];   // [B, T, C]
    float* out = (float*)d_out;                // F_s_updated ++ F_t_updated

    (void)in_sizes; (void)n_in; (void)out_size;

    dim3 g1(HW / 32, BATCH);
    k1_scores_softmax<<<g1, 256>>>(Fs, Ft);

    dim3 g2(HW / 64, C_DIM / 64, BATCH);
    k2_spatial<<<g2, 256>>>(Fs, Ft, out);

    dim3 g3(T_DIM / 64, C_DIM / 64, BATCH);
    k3_text<<<g3, 256>>>(Fs, out + (size_t)BATCH * C_DIM * HW);
}

// round 4
// speedup vs baseline: 1.6632x; 1.6632x over previous
#include <cuda_runtime.h>
#include <cuda_bf16.h>
#include <math_constants.h>

#define BATCH 8
#define C_DIM 256
#define HW    4096
#define T_DIM 512

// 1/sqrt(512)
#define SCALE 0.044194173824159220275f

// scratch: probabilities S [B][HW][T] (64 MiB), split-K partials (16 MiB)
__device__ float g_S[(size_t)BATCH * HW * T_DIM];
__device__ float g_P[(size_t)4 * BATCH * T_DIM * C_DIM];

typedef unsigned long long u64;

__device__ __forceinline__ u64 pack2(float lo, float hi) {
    u64 r; asm("mov.b64 %0, {%1, %2};" : "=l"(r) : "f"(lo), "f"(hi)); return r;
}
__device__ __forceinline__ void unpack2(u64 v, float& lo, float& hi) {
    asm("mov.b64 {%0, %1}, %2;" : "=f"(lo), "=f"(hi) : "l"(v));
}
__device__ __forceinline__ u64 ffma2(u64 a, u64 b, u64 c) {
    u64 d; asm("fma.rn.f32x2 %0, %1, %2, %3;" : "=l"(d) : "l"(a), "l"(b), "l"(c)); return d;
}

// ---------------------------------------------------------------------
// Shared micro-kernel geometry (all GEMMs): BM=BN=128, BK=16, 256 thr.
// 8 warps = 4(m) x 2(n). lanes: lm = lane/8 (0..3), ln = lane%8 (0..7).
// thread rows: wm*32 + lm*4 + {0..3}  and  wm*32 + 16 + lm*4 + {0..3}
// thread cols: wn*64 + ln*4 + {0..3}  and  wn*64 + 32 + ln*4 + {0..3}
// A LDS.128: 4 distinct addrs/warp (8-lane broadcast), contiguous 64B.
// B LDS.128: 8 distinct addrs/warp (4-lane broadcast), contiguous 128B.
// ---------------------------------------------------------------------
#define SMEM_STRIDE 132

#define GEMM_CORE_DECL()                                                     \
    const int tid  = threadIdx.x;                                            \
    const int lane = tid & 31;                                               \
    const int warp = tid >> 5;                                               \
    const int wm = warp & 3, wn = warp >> 2;                                 \
    const int lm = lane >> 3, ln = lane & 7;                                 \
    const int ra = wm * 32 + lm * 4;      /* rows ra..ra+3, ra+16..ra+19 */  \
    const int ca = wn * 64 + ln * 4;      /* cols ca..ca+3, ca+32..ca+35 */  \
    u64 acc[8][4];                                                           \
    _Pragma("unroll") for (int i = 0; i < 8; i++)                            \
        _Pragma("unroll") for (int j = 0; j < 4; j++) acc[i][j] = 0ULL;

#define GEMM_CORE_STEP(As, Bs)                                               \
    _Pragma("unroll")                                                        \
    for (int k = 0; k < 16; k++) {                                           \
        float4 a0 = *reinterpret_cast<const float4*>(&As[k][ra]);            \
        float4 a1 = *reinterpret_cast<const float4*>(&As[k][ra + 16]);       \
        float4 b0 = *reinterpret_cast<const float4*>(&Bs[k][ca]);            \
        float4 b1 = *reinterpret_cast<const float4*>(&Bs[k][ca + 32]);       \
        u64 bb[4] = { pack2(b0.x, b0.y), pack2(b0.z, b0.w),                  \
                      pack2(b1.x, b1.y), pack2(b1.z, b1.w) };                \
        float av[8] = { a0.x, a0.y, a0.z, a0.w, a1.x, a1.y, a1.z, a1.w };    \
        _Pragma("unroll")                                                    \
        for (int i = 0; i < 8; i++) {                                        \
            u64 aa = pack2(av[i], av[i]);                                    \
            _Pragma("unroll")                                                 \
            for (int j = 0; j < 4; j++) acc[i][j] = ffma2(aa, bb[j], acc[i][j]); \
        }                                                                    \
    }

__device__ __forceinline__ int row_of(int ra, int i) {
    return ra + (i < 4 ? i : 12 + i);   // i>=4 -> ra+16+(i-4)
}

// =====================================================================
// GEMM1: S_raw[b][n][t] = sum_c Fs[b][c][n] * Ft[b][t][c]
// M=n (4096), N=t (512), K=c (256)
// =====================================================================
__global__ __launch_bounds__(256) void k_gemm1(
    const float* __restrict__ Fs, const float* __restrict__ Ft)
{
    __shared__ __align__(16) float As[16][SMEM_STRIDE];
    __shared__ __align__(16) float Bs[16][SMEM_STRIDE];

    const int b  = blockIdx.z;
    const int n0 = blockIdx.x * 128;
    const int t0 = blockIdx.y * 128;
    const float* FsB = Fs + (size_t)b * C_DIM * HW;
    const float* FtB = Ft + (size_t)b * T_DIM * C_DIM;
    float* Sb = g_S + (size_t)b * HW * T_DIM;

    GEMM_CORE_DECL();

    for (int k0 = 0; k0 < C_DIM; k0 += 16) {
        // A direct: As[kk][mm] = Fs[c=k0+kk][n0+mm]  (contig in n)
#pragma unroll
        for (int r = 0; r < 2; r++) {
            int u = tid + r * 256;
            int kk = u >> 5, mm = (u & 31) * 4;
            *reinterpret_cast<float4*>(&As[kk][mm]) =
                *reinterpret_cast<const float4*>(&FsB[(size_t)(k0 + kk) * HW + n0 + mm]);
        }
        // B transpose: Bs[kk][tt] = Ft[t0+tt][c=k0+kk]  (contig in c)
#pragma unroll
        for (int r = 0; r < 2; r++) {
            int u = tid + r * 256;
            int tt = u >> 2, kq = (u & 3) * 4;
            float4 v = *reinterpret_cast<const float4*>(&FtB[(size_t)(t0 + tt) * C_DIM + k0 + kq]);
            Bs[kq + 0][tt] = v.x; Bs[kq + 1][tt] = v.y;
            Bs[kq + 2][tt] = v.z; Bs[kq + 3][tt] = v.w;
        }
        __syncthreads();
        GEMM_CORE_STEP(As, Bs);
        __syncthreads();
    }

#pragma unroll
    for (int i = 0; i < 8; i++) {
        int n = n0 + row_of(ra, i);
        float* dst = Sb + (size_t)n * T_DIM + t0;
        float4 o0, o1;
        unpack2(acc[i][0], o0.x, o0.y); unpack2(acc[i][1], o0.z, o0.w);
        unpack2(acc[i][2], o1.x, o1.y); unpack2(acc[i][3], o1.z, o1.w);
        *reinterpret_cast<float4*>(&dst[ca])      = o0;
        *reinterpret_cast<float4*>(&dst[ca + 32]) = o1;
    }
}

// =====================================================================
// Softmax over t (last axis), in place on g_S. One warp per row of 512.
// =====================================================================
__global__ __launch_bounds__(256) void k_softmax()
{
    const int row  = blockIdx.x * 8 + (threadIdx.x >> 5);
    const int lane = threadIdx.x & 31;
    float* p = g_S + (size_t)row * T_DIM;

    float v[16];
#pragma unroll
    for (int q = 0; q < 4; q++) {
        float4 f = *reinterpret_cast<const float4*>(&p[lane * 4 + q * 128]);
        v[q * 4 + 0] = f.x; v[q * 4 + 1] = f.y; v[q * 4 + 2] = f.z; v[q * 4 + 3] = f.w;
    }
    float mx = -CUDART_INF_F;
#pragma unroll
    for (int x = 0; x < 16; x++) { v[x] *= SCALE; mx = fmaxf(mx, v[x]); }
#pragma unroll
    for (int off = 16; off >= 1; off >>= 1)
        mx = fmaxf(mx, __shfl_xor_sync(0xffffffffu, mx, off));
    float s = 0.0f;
#pragma unroll
    for (int x = 0; x < 16; x++) { v[x] = __expf(v[x] - mx); s += v[x]; }
#pragma unroll
    for (int off = 16; off >= 1; off >>= 1)
        s += __shfl_xor_sync(0xffffffffu, s, off);
    float inv = 1.0f / s;
#pragma unroll
    for (int q = 0; q < 4; q++) {
        float4 f = make_float4(v[q*4+0]*inv, v[q*4+1]*inv, v[q*4+2]*inv, v[q*4+3]*inv);
        *reinterpret_cast<float4*>(&p[lane * 4 + q * 128]) = f;
    }
}

// =====================================================================
// GEMM2: out[b][c][n] = Fs[b][c][n] + sum_t S[b][n][t] * Ft[b][t][c]
// M=c (256), N=n (4096), K=t (512)
// =====================================================================
__global__ __launch_bounds__(256) void k_gemm2(
    const float* __restrict__ Fs, const float* __restrict__ Ft,
    float* __restrict__ out)
{
    __shared__ __align__(16) float As[16][SMEM_STRIDE];
    __shared__ __align__(16) float Bs[16][SMEM_STRIDE];

    const int b  = blockIdx.z;
    const int n0 = blockIdx.x * 128;
    const int c0 = blockIdx.y * 128;
    const float* FsB = Fs + (size_t)b * C_DIM * HW;
    const float* FtB = Ft + (size_t)b * T_DIM * C_DIM;
    const float* Sb  = g_S + (size_t)b * HW * T_DIM;
    float* outB = out + (size_t)b * C_DIM * HW;

    GEMM_CORE_DECL();

    for (int k0 = 0; k0 < T_DIM; k0 += 16) {
        // A direct: As[kk][mm] = Ft[t=k0+kk][c0+mm]  (contig in c)
#pragma unroll
        for (int r = 0; r < 2; r++) {
            int u = tid + r * 256;
            int kk = u >> 5, mm = (u & 31) * 4;
            *reinterpret_cast<float4*>(&As[kk][mm]) =
                *reinterpret_cast<const float4*>(&FtB[(size_t)(k0 + kk) * C_DIM + c0 + mm]);
        }
        // B transpose: Bs[kk][nn] = S[n0+nn][t=k0+kk]  (contig in t)
#pragma unroll
        for (int r = 0; r < 2; r++) {
            int u = tid + r * 256;
            int nn = u >> 2, kq = (u & 3) * 4;
            float4 v = *reinterpret_cast<const float4*>(&Sb[(size_t)(n0 + nn) * T_DIM + k0 + kq]);
            Bs[kq + 0][nn] = v.x; Bs[kq + 1][nn] = v.y;
            Bs[kq + 2][nn] = v.z; Bs[kq + 3][nn] = v.w;
        }
        __syncthreads();
        GEMM_CORE_STEP(As, Bs);
        __syncthreads();
    }

#pragma unroll
    for (int i = 0; i < 8; i++) {
        int c = c0 + row_of(ra, i);
        size_t base = (size_t)c * HW + n0;
        float4 o0, o1;
        unpack2(acc[i][0], o0.x, o0.y); unpack2(acc[i][1], o0.z, o0.w);
        unpack2(acc[i][2], o1.x, o1.y); unpack2(acc[i][3], o1.z, o1.w);
        float4 f0 = *reinterpret_cast<const float4*>(&FsB[base + ca]);
        float4 f1 = *reinterpret_cast<const float4*>(&FsB[base + ca + 32]);
        o0.x += f0.x; o0.y += f0.y; o0.z += f0.z; o0.w += f0.w;
        o1.x += f1.x; o1.y += f1.y; o1.z += f1.z; o1.w += f1.w;
        *reinterpret_cast<float4*>(&outB[base + ca])      = o0;
        *reinterpret_cast<float4*>(&outB[base + ca + 32]) = o1;
    }
}

// =====================================================================
// GEMM3 (split-K=4): P[s][b][t][c] = sum_{n in chunk s} S[b][n][t]*Fs[b][c][n]
// M=t (512), N=c (256), K=n (4096, 1024 per split)
// grid: x = split (4), y = tile (4 t-tiles x 2 c-tiles), z = b
// =====================================================================
__global__ __launch_bounds__(256) void k_gemm3(const float* __restrict__ Fs)
{
    __shared__ __align__(16) float As[16][SMEM_STRIDE];
    __shared__ __align__(16) float Bs[16][SMEM_STRIDE];

    const int b  = blockIdx.z;
    const int t0 = (blockIdx.y & 3) * 128;
    const int c0 = (blockIdx.y >> 2) * 128;
    const int ks = blockIdx.x * 1024;
    const float* FsB = Fs + (size_t)b * C_DIM * HW;
    const float* Sb  = g_S + (size_t)b * HW * T_DIM;
    float* Pp = g_P + (size_t)blockIdx.x * BATCH * T_DIM * C_DIM
                    + (size_t)b * T_DIM * C_DIM;

    GEMM_CORE_DECL();

    for (int kq0 = 0; kq0 < 1024; kq0 += 16) {
        int k0 = ks + kq0;
        // A direct: As[kk][mm] = S[n=k0+kk][t0+mm]  (contig in t)
#pragma unroll
        for (int r = 0; r < 2; r++) {
            int u = tid + r * 256;
            int kk = u >> 5, mm = (u & 31) * 4;
            *reinterpret_cast<float4*>(&As[kk][mm]) =
                *reinterpret_cast<const float4*>(&Sb[(size_t)(k0 + kk) * T_DIM + t0 + mm]);
        }
        // B transpose: Bs[kk][cc] = Fs[c0+cc][n=k0+kk]  (contig in n)
#pragma unroll
        for (int r = 0; r < 2; r++) {
            int u = tid + r * 256;
            int cc = u >> 2, kq = (u & 3) * 4;
            float4 v = *reinterpret_cast<const float4*>(&FsB[(size_t)(c0 + cc) * HW + k0 + kq]);
            Bs[kq + 0][cc] = v.x; Bs[kq + 1][cc] = v.y;
            Bs[kq + 2][cc] = v.z; Bs[kq + 3][cc] = v.w;
        }
        __syncthreads();
        GEMM_CORE_STEP(As, Bs);
        __syncthreads();
    }

#pragma unroll
    for (int i = 0; i < 8; i++) {
        int t = t0 + row_of(ra, i);
        float* dst = Pp + (size_t)t * C_DIM + c0;
        float4 o0, o1;
        unpack2(acc[i][0], o0.x, o0.y); unpack2(acc[i][1], o0.z, o0.w);
        unpack2(acc[i][2], o1.x, o1.y); unpack2(acc[i][3], o1.z, o1.w);
        *reinterpret_cast<float4*>(&dst[ca])      = o0;
        *reinterpret_cast<float4*>(&dst[ca + 32]) = o1;
    }
}

// =====================================================================
// Reduce 4 split-K slabs -> F_t_updated part of d_out
// =====================================================================
__global__ __launch_bounds__(256) void k_reduce(float* __restrict__ outT)
{
    const size_t SLAB = (size_t)BATCH * T_DIM * C_DIM;   // 1,048,576
    size_t idx = ((size_t)blockIdx.x * 256 + threadIdx.x) * 4;
    float4 a = *reinterpret_cast<const float4*>(&g_P[idx]);
    float4 c = *reinterpret_cast<const float4*>(&g_P[idx + SLAB]);
    float4 d = *reinterpret_cast<const float4*>(&g_P[idx + 2 * SLAB]);
    float4 e = *reinterpret_cast<const float4*>(&g_P[idx + 3 * SLAB]);
    a.x += c.x + d.x + e.x; a.y += c.y + d.y + e.y;
    a.z += c.z + d.z + e.z; a.w += c.w + d.w + e.w;
    *reinterpret_cast<float4*>(&outT[idx]) = a;
}

// =====================================================================
extern "C" void kernel_launch(void* const* d_in, const int* in_sizes, int n_in,
                              void* d_out, int out_size)
{
    const float* Fs = (const float*)d_in[0];   // [B, C, H, W]
    const float* Ft = (const float*)d_in[1];   // [B, T, C]
    float* out = (float*)d_out;
    (void)in_sizes; (void)n_in; (void)out_size;

    k_gemm1<<<dim3(HW / 128, T_DIM / 128, BATCH), 256>>>(Fs, Ft);
    k_softmax<<<(BATCH * HW) / 8, 256>>>();
    k_gemm2<<<dim3(HW / 128, C_DIM / 128, BATCH), 256>>>(Fs, Ft, out);
    k_gemm3<<<dim3(4, 8, BATCH), 256>>>(Fs);
    k_reduce<<<(BATCH * T_DIM * C_DIM) / (256 * 4), 256>>>(
        out + (size_t)BATCH * C_DIM * HW);
}

// round 9
// speedup vs baseline: 2.0385x; 1.2257x over previous
#include <cuda_runtime.h>
#include <cuda_bf16.h>
#include <math_constants.h>

#define BATCH 8
#define C_DIM 256
#define HW    4096
#define T_DIM 512

#define SCALE 0.044194173824159220275f   // 1/sqrt(512)

__device__ float g_S[(size_t)BATCH * HW * T_DIM];
__device__ float g_P[(size_t)4 * BATCH * T_DIM * C_DIM];

typedef unsigned long long u64;
typedef unsigned int u32;

__device__ __forceinline__ u64 pack2(float lo, float hi) {
    u64 r; asm("mov.b64 %0, {%1, %2};" : "=l"(r) : "f"(lo), "f"(hi)); return r;
}
__device__ __forceinline__ void unpack2(u64 v, float& lo, float& hi) {
    asm("mov.b64 {%0, %1}, %2;" : "=f"(lo), "=f"(hi) : "l"(v));
}
__device__ __forceinline__ u64 ffma2(u64 a, u64 b, u64 c) {
    u64 d; asm("fma.rn.f32x2 %0, %1, %2, %3;" : "=l"(d) : "l"(a), "l"(b), "l"(c)); return d;
}
__device__ __forceinline__ void cp16(u32 smem_dst, const void* gsrc) {
    asm volatile("cp.async.cg.shared.global [%0], [%1], 16;"
                 :: "r"(smem_dst), "l"(gsrc));
}
__device__ __forceinline__ void cp_commit() {
    asm volatile("cp.async.commit_group;");
}
__device__ __forceinline__ void cp_wait0() {
    asm volatile("cp.async.wait_group 0;");
}

// ---------------------------------------------------------------------
// Core geometry: BM=BN=128, BK=16, 256 thr, 8x8 micro-tile per thread.
// 8 warps = 4(m) x 2(n); lm = lane/8, ln = lane%8.
// A LDS.128 8-lane broadcast, B LDS.128 4-lane broadcast (conflict-free).
// ---------------------------------------------------------------------
#define SMEM_STRIDE 132

#define GEMM_CORE_DECL()                                                     \
    const int tid  = threadIdx.x;                                            \
    const int lane = tid & 31;                                               \
    const int warp = tid >> 5;                                               \
    const int wm = warp & 3, wn = warp >> 2;                                 \
    const int lm = lane >> 3, ln = lane & 7;                                 \
    const int ra = wm * 32 + lm * 4;                                         \
    const int ca = wn * 64 + ln * 4;                                         \
    u64 acc[8][4];                                                           \
    _Pragma("unroll") for (int i = 0; i < 8; i++)                            \
        _Pragma("unroll") for (int j = 0; j < 4; j++) acc[i][j] = 0ULL;

#define GEMM_CORE_STEP(As, Bs)                                               \
    _Pragma("unroll")                                                        \
    for (int k = 0; k < 16; k++) {                                           \
        float4 a0 = *reinterpret_cast<const float4*>(&As[k][ra]);            \
        float4 a1 = *reinterpret_cast<const float4*>(&As[k][ra + 16]);       \
        float4 b0 = *reinterpret_cast<const float4*>(&Bs[k][ca]);            \
        float4 b1 = *reinterpret_cast<const float4*>(&Bs[k][ca + 32]);       \
        u64 bb[4] = { pack2(b0.x, b0.y), pack2(b0.z, b0.w),                  \
                      pack2(b1.x, b1.y), pack2(b1.z, b1.w) };                \
        float av[8] = { a0.x, a0.y, a0.z, a0.w, a1.x, a1.y, a1.z, a1.w };    \
        _Pragma("unroll")                                                    \
        for (int i = 0; i < 8; i++) {                                        \
            u64 aa = pack2(av[i], av[i]);                                    \
            _Pragma("unroll")                                                 \
            for (int j = 0; j < 4; j++) acc[i][j] = ffma2(aa, bb[j], acc[i][j]); \
        }                                                                    \
    }

__device__ __forceinline__ int row_of(int ra, int i) {
    return ra + (i < 4 ? i : 12 + i);
}

// =====================================================================
// GEMM1: S_raw[b][n][t] = sum_c Fs[b][c][n] * Ft[b][t][c]
// A (direct, cp.async): Fs[c][n];  B (transpose, regs): Ft[t][c]
// =====================================================================
__global__ __launch_bounds__(256, 2) void k_gemm1(
    const float* __restrict__ Fs, const float* __restrict__ Ft)
{
    __shared__ __align__(16) float As[2][16][SMEM_STRIDE];
    __shared__ __align__(16) float Bs[2][16][SMEM_STRIDE];

    const int b  = blockIdx.z;
    const int n0 = blockIdx.x * 128;
    const int t0 = blockIdx.y * 128;
    const float* FsB = Fs + (size_t)b * C_DIM * HW;
    const float* FtB = Ft + (size_t)b * T_DIM * C_DIM;
    float* Sb = g_S + (size_t)b * HW * T_DIM;

    GEMM_CORE_DECL();

    const int kkA = tid >> 5, mmA = (tid & 31) * 4;           // u = tid
    const int kkA2 = (tid + 256) >> 5, mmA2 = mmA;            // u = tid+256
    const int ttB = tid >> 2, kqB = (tid & 3) * 4;            // u = tid (B row 0..63)
    const int ttB2 = ttB + 64;                                 // u = tid+256

    const int NIT = C_DIM / 16;

#define G1_ISSUE_A(k0, buf)                                                  \
    cp16((u32)__cvta_generic_to_shared(&As[buf][kkA][mmA]),                  \
         &FsB[(size_t)((k0) + kkA) * HW + n0 + mmA]);                        \
    cp16((u32)__cvta_generic_to_shared(&As[buf][kkA2][mmA2]),                \
         &FsB[(size_t)((k0) + kkA2) * HW + n0 + mmA2]);                      \
    cp_commit();

#define G1_LOAD_B(k0)                                                        \
    vB0 = *reinterpret_cast<const float4*>(&FtB[(size_t)(t0 + ttB)  * C_DIM + (k0) + kqB]); \
    vB1 = *reinterpret_cast<const float4*>(&FtB[(size_t)(t0 + ttB2) * C_DIM + (k0) + kqB]);

#define G1_STORE_B(buf)                                                      \
    Bs[buf][kqB+0][ttB]  = vB0.x; Bs[buf][kqB+1][ttB]  = vB0.y;              \
    Bs[buf][kqB+2][ttB]  = vB0.z; Bs[buf][kqB+3][ttB]  = vB0.w;              \
    Bs[buf][kqB+0][ttB2] = vB1.x; Bs[buf][kqB+1][ttB2] = vB1.y;              \
    Bs[buf][kqB+2][ttB2] = vB1.z; Bs[buf][kqB+3][ttB2] = vB1.w;

    float4 vB0, vB1;
    G1_ISSUE_A(0, 0);
    G1_LOAD_B(0);
    cp_wait0();
    G1_STORE_B(0);
    __syncthreads();

    for (int it = 0; it < NIT; it++) {
        const int cur = it & 1, nxt = cur ^ 1;
        if (it + 1 < NIT) {
            G1_ISSUE_A((it + 1) * 16, nxt);
            G1_LOAD_B((it + 1) * 16);
        }
        GEMM_CORE_STEP(As[cur], Bs[cur]);
        if (it + 1 < NIT) {
            cp_wait0();
            G1_STORE_B(nxt);
        }
        __syncthreads();
    }

#pragma unroll
    for (int i = 0; i < 8; i++) {
        int n = n0 + row_of(ra, i);
        float* dst = Sb + (size_t)n * T_DIM + t0;
        float4 o0, o1;
        unpack2(acc[i][0], o0.x, o0.y); unpack2(acc[i][1], o0.z, o0.w);
        unpack2(acc[i][2], o1.x, o1.y); unpack2(acc[i][3], o1.z, o1.w);
        *reinterpret_cast<float4*>(&dst[ca])      = o0;
        *reinterpret_cast<float4*>(&dst[ca + 32]) = o1;
    }
}

// =====================================================================
// Softmax over t, in place on g_S. One warp per row of 512.
// =====================================================================
__global__ __launch_bounds__(256) void k_softmax()
{
    const int row  = blockIdx.x * 8 + (threadIdx.x >> 5);
    const int lane = threadIdx.x & 31;
    float* p = g_S + (size_t)row * T_DIM;

    float v[16];
#pragma unroll
    for (int q = 0; q < 4; q++) {
        float4 f = *reinterpret_cast<const float4*>(&p[lane * 4 + q * 128]);
        v[q*4+0] = f.x; v[q*4+1] = f.y; v[q*4+2] = f.z; v[q*4+3] = f.w;
    }
    float mx = -CUDART_INF_F;
#pragma unroll
    for (int x = 0; x < 16; x++) { v[x] *= SCALE; mx = fmaxf(mx, v[x]); }
#pragma unroll
    for (int off = 16; off >= 1; off >>= 1)
        mx = fmaxf(mx, __shfl_xor_sync(0xffffffffu, mx, off));
    float s = 0.0f;
#pragma unroll
    for (int x = 0; x < 16; x++) { v[x] = __expf(v[x] - mx); s += v[x]; }
#pragma unroll
    for (int off = 16; off >= 1; off >>= 1)
        s += __shfl_xor_sync(0xffffffffu, s, off);
    float inv = 1.0f / s;
#pragma unroll
    for (int q = 0; q < 4; q++) {
        float4 f = make_float4(v[q*4+0]*inv, v[q*4+1]*inv, v[q*4+2]*inv, v[q*4+3]*inv);
        *reinterpret_cast<float4*>(&p[lane * 4 + q * 128]) = f;
    }
}

// =====================================================================
// GEMM2: out[b][c][n] = Fs[b][c][n] + sum_t S[b][n][t] * Ft[b][t][c]
// A (direct, cp.async): Ft[t][c];  B (transpose, regs): S[n][t]
// =====================================================================
__global__ __launch_bounds__(256, 2) void k_gemm2(
    const float* __restrict__ Fs, const float* __restrict__ Ft,
    float* __restrict__ out)
{
    __shared__ __align__(16) float As[2][16][SMEM_STRIDE];
    __shared__ __align__(16) float Bs[2][16][SMEM_STRIDE];

    const int b  = blockIdx.z;
    const int n0 = blockIdx.x * 128;
    const int c0 = blockIdx.y * 128;
    const float* FsB = Fs + (size_t)b * C_DIM * HW;
    const float* FtB = Ft + (size_t)b * T_DIM * C_DIM;
    const float* Sb  = g_S + (size_t)b * HW * T_DIM;
    float* outB = out + (size_t)b * C_DIM * HW;

    GEMM_CORE_DECL();

    const int kkA = tid >> 5, mmA = (tid & 31) * 4;
    const int kkA2 = (tid + 256) >> 5;
    const int nnB = tid >> 2, kqB = (tid & 3) * 4;
    const int nnB2 = nnB + 64;

    const int NIT = T_DIM / 16;

#define G2_ISSUE_A(k0, buf)                                                  \
    cp16((u32)__cvta_generic_to_shared(&As[buf][kkA][mmA]),                  \
         &FtB[(size_t)((k0) + kkA) * C_DIM + c0 + mmA]);                     \
    cp16((u32)__cvta_generic_to_shared(&As[buf][kkA2][mmA]),                 \
         &FtB[(size_t)((k0) + kkA2) * C_DIM + c0 + mmA]);                    \
    cp_commit();

#define G2_LOAD_B(k0)                                                        \
    vB0 = *reinterpret_cast<const float4*>(&Sb[(size_t)(n0 + nnB)  * T_DIM + (k0) + kqB]); \
    vB1 = *reinterpret_cast<const float4*>(&Sb[(size_t)(n0 + nnB2) * T_DIM + (k0) + kqB]);

#define G2_STORE_B(buf)                                                      \
    Bs[buf][kqB+0][nnB]  = vB0.x; Bs[buf][kqB+1][nnB]  = vB0.y;              \
    Bs[buf][kqB+2][nnB]  = vB0.z; Bs[buf][kqB+3][nnB]  = vB0.w;              \
    Bs[buf][kqB+0][nnB2] = vB1.x; Bs[buf][kqB+1][nnB2] = vB1.y;              \
    Bs[buf][kqB+2][nnB2] = vB1.z; Bs[buf][kqB+3][nnB2] = vB1.w;

    float4 vB0, vB1;
    G2_ISSUE_A(0, 0);
    G2_LOAD_B(0);
    cp_wait0();
    G2_STORE_B(0);
    __syncthreads();

    for (int it = 0; it < NIT; it++) {
        const int cur = it & 1, nxt = cur ^ 1;
        if (it + 1 < NIT) {
            G2_ISSUE_A((it + 1) * 16, nxt);
            G2_LOAD_B((it + 1) * 16);
        }
        GEMM_CORE_STEP(As[cur], Bs[cur]);
        if (it + 1 < NIT) {
            cp_wait0();
            G2_STORE_B(nxt);
        }
        __syncthreads();
    }

#pragma unroll
    for (int i = 0; i < 8; i++) {
        int c = c0 + row_of(ra, i);
        size_t base = (size_t)c * HW + n0;
        float4 o0, o1;
        unpack2(acc[i][0], o0.x, o0.y); unpack2(acc[i][1], o0.z, o0.w);
        unpack2(acc[i][2], o1.x, o1.y); unpack2(acc[i][3], o1.z, o1.w);
        float4 f0 = *reinterpret_cast<const float4*>(&FsB[base + ca]);
        float4 f1 = *reinterpret_cast<const float4*>(&FsB[base + ca + 32]);
        o0.x += f0.x; o0.y += f0.y; o0.z += f0.z; o0.w += f0.w;
        o1.x += f1.x; o1.y += f1.y; o1.z += f1.z; o1.w += f1.w;
        *reinterpret_cast<float4*>(&outB[base + ca])      = o0;
        *reinterpret_cast<float4*>(&outB[base + ca + 32]) = o1;
    }
}

// =====================================================================
// GEMM3 (split-K=4): P[s][b][t][c] = sum_{n chunk} S[b][n][t] * Fs[b][c][n]
// A (direct, cp.async): S[n][t];  B (transpose, regs): Fs[c][n]
// =====================================================================
__global__ __launch_bounds__(256, 2) void k_gemm3(const float* __restrict__ Fs)
{
    __shared__ __align__(16) float As[2][16][SMEM_STRIDE];
    __shared__ __align__(16) float Bs[2][16][SMEM_STRIDE];

    const int b  = blockIdx.z;
    const int t0 = (blockIdx.y & 3) * 128;
    const int c0 = (blockIdx.y >> 2) * 128;
    const int ks = blockIdx.x * 1024;
    const float* FsB = Fs + (size_t)b * C_DIM * HW;
    const float* Sb  = g_S + (size_t)b * HW * T_DIM;
    float* Pp = g_P + (size_t)blockIdx.x * BATCH * T_DIM * C_DIM
                    + (size_t)b * T_DIM * C_DIM;

    GEMM_CORE_DECL();

    const int kkA = tid >> 5, mmA = (tid & 31) * 4;
    const int kkA2 = (tid + 256) >> 5;
    const int ccB = tid >> 2, kqB = (tid & 3) * 4;
    const int ccB2 = ccB + 64;

    const int NIT = 1024 / 16;

#define G3_ISSUE_A(k0, buf)                                                  \
    cp16((u32)__cvta_generic_to_shared(&As[buf][kkA][mmA]),                  \
         &Sb[(size_t)((k0) + kkA) * T_DIM + t0 + mmA]);                      \
    cp16((u32)__cvta_generic_to_shared(&As[buf][kkA2][mmA]),                 \
         &Sb[(size_t)((k0) + kkA2) * T_DIM + t0 + mmA]);                     \
    cp_commit();

#define G3_LOAD_B(k0)                                                        \
    vB0 = *reinterpret_cast<const float4*>(&FsB[(size_t)(c0 + ccB)  * HW + (k0) + kqB]); \
    vB1 = *reinterpret_cast<const float4*>(&FsB[(size_t)(c0 + ccB2) * HW + (k0) + kqB]);

#define G3_STORE_B(buf)                                                      \
    Bs[buf][kqB+0][ccB]  = vB0.x; Bs[buf][kqB+1][ccB]  = vB0.y;              \
    Bs[buf][kqB+2][ccB]  = vB0.z; Bs[buf][kqB+3][ccB]  = vB0.w;              \
    Bs[buf][kqB+0][ccB2] = vB1.x; Bs[buf][kqB+1][ccB2] = vB1.y;              \
    Bs[buf][kqB+2][ccB2] = vB1.z; Bs[buf][kqB+3][ccB2] = vB1.w;

    float4 vB0, vB1;
    G3_ISSUE_A(ks, 0);
    G3_LOAD_B(ks);
    cp_wait0();
    G3_STORE_B(0);
    __syncthreads();

    for (int it = 0; it < NIT; it++) {
        const int cur = it & 1, nxt = cur ^ 1;
        if (it + 1 < NIT) {
            G3_ISSUE_A(ks + (it + 1) * 16, nxt);
            G3_LOAD_B(ks + (it + 1) * 16);
        }
        GEMM_CORE_STEP(As[cur], Bs[cur]);
        if (it + 1 < NIT) {
            cp_wait0();
            G3_STORE_B(nxt);
        }
        __syncthreads();
    }

#pragma unroll
    for (int i = 0; i < 8; i++) {
        int t = t0 + row_of(ra, i);
        float* dst = Pp + (size_t)t * C_DIM + c0;
        float4 o0, o1;
        unpack2(acc[i][0], o0.x, o0.y); unpack2(acc[i][1], o0.z, o0.w);
        unpack2(acc[i][2], o1.x, o1.y); unpack2(acc[i][3], o1.z, o1.w);
        *reinterpret_cast<float4*>(&dst[ca])      = o0;
        *reinterpret_cast<float4*>(&dst[ca + 32]) = o1;
    }
}

// =====================================================================
// Reduce 4 split-K slabs -> F_t_updated part of d_out
// =====================================================================
__global__ __launch_bounds__(256) void k_reduce(float* __restrict__ outT)
{
    const size_t SLAB = (size_t)BATCH * T_DIM * C_DIM;
    size_t idx = ((size_t)blockIdx.x * 256 + threadIdx.x) * 4;
    float4 a = *reinterpret_cast<const float4*>(&g_P[idx]);
    float4 c = *reinterpret_cast<const float4*>(&g_P[idx + SLAB]);
    float4 d = *reinterpret_cast<const float4*>(&g_P[idx + 2 * SLAB]);
    float4 e = *reinterpret_cast<const float4*>(&g_P[idx + 3 * SLAB]);
    a.x += c.x + d.x + e.x; a.y += c.y + d.y + e.y;
    a.z += c.z + d.z + e.z; a.w += c.w + d.w + e.w;
    *reinterpret_cast<float4*>(&outT[idx]) = a;
}

// =====================================================================
extern "C" void kernel_launch(void* const* d_in, const int* in_sizes, int n_in,
                              void* d_out, int out_size)
{
    const float* Fs = (const float*)d_in[0];   // [B, C, H, W]
    const float* Ft = (const float*)d_in[1];   // [B, T, C]
    float* out = (float*)d_out;
    (void)in_sizes; (void)n_in; (void)out_size;

    k_gemm1<<<dim3(HW / 128, T_DIM / 128, BATCH), 256>>>(Fs, Ft);
    k_softmax<<<(BATCH * HW) / 8, 256>>>();
    k_gemm2<<<dim3(HW / 128, C_DIM / 128, BATCH), 256>>>(Fs, Ft, out);
    k_gemm3<<<dim3(4, 8, BATCH), 256>>>(Fs);
    k_reduce<<<(BATCH * T_DIM * C_DIM) / (256 * 4), 256>>>(
        out + (size_t)BATCH * C_DIM * HW);
}